// round 11
// baseline (speedup 1.0000x reference)
#include <cuda_runtime.h>
#include <cstdint>

// ---------------------------------------------------------------------------
// Problem constants
// ---------------------------------------------------------------------------
#define BATCH   1024
#define D_SZ    384
#define K_WIDE  (D_SZ * D_SZ)      // 147456
#define N_OUT   (2 * D_SZ)         // 768
#define OUT_STR (4 * D_SZ)         // 1536

// ---------------------------------------------------------------------------
// Wide-path GEMM config: M=1024 N=768 K=147456, A = hs x ht generated on-fly
// R10: TRANSPOSED mma roles. W2 is the A-operand (mma m-dim = W2 rows, 4-reg
// fragment from SMEM, reused across 8 batch-subtiles -> 0.5 LDS/mma, halving
// crossbar traffic vs R9's 1 LDS/mma). The hs*ht product is the B-operand,
// built in registers (htv cached per j-block, hs scalar per chunk).
// ---------------------------------------------------------------------------
#define BM      128                 // batch tile
#define BN      128                 // W2-row tile
#define BKC     32                  // k-floats per chunk
#define KSPLIT  3
#define KSLICE  (K_WIDE / KSPLIT)   // 49152 = 128 i-values
#define IPG     8                   // i-values per hs staging group
#define NCH     (KSLICE / BKC)      // 1536 chunks per CTA
#define NPAIR   (NCH / 2)           // 768 pipeline iterations (2 chunks each)
#define LDT     36                  // row stride words: 32 + 4 pad (conflict-free)
#define HSS_LD  10                  // Hss row stride: 10r mod 32 distinct for r<8
#define NTH     512
#define NBUF    6                   // 3-deep ring of chunk PAIRS

// Truncation-bias compensation (R8, kept): both mma operands HW-truncate
// fp32->tf32; pre-scaling hs by (1 + 2^-10 * ln2) cancels the expected
// relative bias of BOTH operands in each product. rel_err ~3.4e-4 measured.
#define HS_COMP 1.000677f

#define B_WORDS   (BN * LDT)            // per W2 chunk buffer (4608 words)
#define HTS_WORDS (BM * LDT)
#define HSS_WORDS (BM * HSS_LD)
#define SMEM_WORDS (NBUF * B_WORDS + HTS_WORDS + HSS_WORDS)
#define SMEM_BYTES (SMEM_WORDS * 4)     // ~134 KB -> dynamic smem, 1 CTA/SM

__device__ __forceinline__ void cp_async16(uint32_t dst, const void* src) {
    asm volatile("cp.async.cg.shared.global [%0], [%1], 16;" :: "r"(dst), "l"(src) : "memory");
}
__device__ __forceinline__ void cp_commit() {
    asm volatile("cp.async.commit_group;" ::: "memory");
}
__device__ __forceinline__ void cp_wait1() {
    asm volatile("cp.async.wait_group 1;" ::: "memory");
}
__device__ __forceinline__ uint32_t smem_u32(const void* p) {
    uint32_t a;
    asm("{ .reg .u64 t; cvta.to.shared.u64 t, %1; cvt.u32.u64 %0, t; }" : "=r"(a) : "l"(p));
    return a;
}

// m16n8k8 tf32 mma; BOTH operands HW-truncated from fp32 bits
__device__ __forceinline__ void mma_tf32(float c[4], const float a[4], float b0, float b1) {
    asm volatile(
        "mma.sync.aligned.m16n8k8.row.col.f32.tf32.tf32.f32 "
        "{%0,%1,%2,%3}, {%4,%5,%6,%7}, {%8,%9}, {%0,%1,%2,%3};\n"
        : "+f"(c[0]), "+f"(c[1]), "+f"(c[2]), "+f"(c[3])
        : "r"(__float_as_uint(a[0])), "r"(__float_as_uint(a[1])),
          "r"(__float_as_uint(a[2])), "r"(__float_as_uint(a[3])),
          "r"(__float_as_uint(b0)), "r"(__float_as_uint(b1)));
}

// ---------------------------------------------------------------------------
// Deep path (passed R1, unchanged):  g = [hs|ht] @ W_L^T + b_L -> out[:,0:768]
// Also initializes out[:,768:1536] = b_L2 for the wide kernel's atomics.
// ---------------------------------------------------------------------------
#define DBM 64
#define DBN 64
#define DBK 16

__global__ __launch_bounds__(256)
void deep_kernel(const float* __restrict__ hs, const float* __restrict__ ht,
                 const float* __restrict__ WL, const float* __restrict__ bL,
                 const float* __restrict__ bL2, float* __restrict__ out)
{
    __shared__ float Xs[DBK][DBM + 8];
    __shared__ float Ws[DBK][DBN + 8];

    const int tid = threadIdx.x;
    const int tx  = tid & 15;
    const int ty  = tid >> 4;
    const int m0  = blockIdx.x * DBM;
    const int n0  = blockIdx.y * DBN;

    float acc[4][4];
#pragma unroll
    for (int i = 0; i < 4; ++i)
#pragma unroll
        for (int j = 0; j < 4; ++j) acc[i][j] = 0.f;

    for (int k0 = 0; k0 < 2 * D_SZ; k0 += DBK) {
        __syncthreads();
#pragma unroll
        for (int q = 0; q < 4; ++q) {
            int e  = tid + 256 * q;
            int kk = e & 15;
            int mm = e >> 4;
            int gk = k0 + kk;
            float xv = (gk < D_SZ) ? hs[(m0 + mm) * D_SZ + gk]
                                   : ht[(m0 + mm) * D_SZ + (gk - D_SZ)];
            Xs[kk][mm] = xv;
            Ws[kk][mm] = WL[(size_t)(n0 + mm) * (2 * D_SZ) + gk];
        }
        __syncthreads();
#pragma unroll
        for (int kk = 0; kk < DBK; ++kk) {
            float4 av = *(const float4*)&Xs[kk][ty * 4];
            float4 bv = *(const float4*)&Ws[kk][tx * 4];
            float a[4] = {av.x, av.y, av.z, av.w};
            float b[4] = {bv.x, bv.y, bv.z, bv.w};
#pragma unroll
            for (int i = 0; i < 4; ++i)
#pragma unroll
                for (int j = 0; j < 4; ++j) acc[i][j] += a[i] * b[j];
        }
    }

#pragma unroll
    for (int i = 0; i < 4; ++i) {
        int row = m0 + ty * 4 + i;
#pragma unroll
        for (int j = 0; j < 4; ++j) {
            int col = n0 + tx * 4 + j;
            out[(size_t)row * OUT_STR + col]         = acc[i][j] + bL[col];
            out[(size_t)row * OUT_STR + N_OUT + col] = bL2[col];
        }
    }
}

// ---------------------------------------------------------------------------
// Wide kernel (transposed mma): 512 threads = 16 warps arranged
// 8 (W2-row groups) x 2 (batch groups). Warp tile: 16 W2-rows x 64 batch.
//   mma m-dim = W2 rows  (A-operand: W2 fragment from SMEM, 4 LDS/ks/warp,
//                         reused across 8 batch-subtiles -> 0.5 LDS/mma)
//   mma n-dim = batch    (B-operand: product hs*ht built in registers:
//                         b0 = hs[m] * ht[m][j], k-index = c / c+4)
// Per warp per chunk: 16 W2-LDS + 8 hs-LDS + 64 FMUL + 32 mma.
// SMEM traffic/chunk ~= 32KB (W2 frags) + 8KB (hs) + 16KB (staging STS)
//  -> ~520 crossbar cyc vs R9's ~830 (the measured bottleneck).
// Pipeline: R9 pairing kept — one cp.async group / wait / barrier per pair;
// ring NBUF=6; issue target (2t+4)%6 last read at iter t-1, drift bounded
// by the barrier at top of iter t.
// ---------------------------------------------------------------------------
__global__ __launch_bounds__(NTH, 1)
void wide_kernel(const float* __restrict__ hs, const float* __restrict__ ht,
                 const float* __restrict__ W2, float* __restrict__ out)
{
    extern __shared__ __align__(16) float smem[];
    float* Bsm = smem;                          // NBUF * BN * LDT (W2 ring)
    float* Hts = smem + NBUF * B_WORDS;         // BM * LDT   (ht j-block)
    float* Hss = Hts + HTS_WORDS;               // BM * HSS_LD ([m][ii] layout)

    const int tid  = threadIdx.x;
    const int lane = tid & 31;
    const int warp = tid >> 5;
    const int wn2 = (warp & 7) * 16;    // W2-row offset (8 groups x 16)
    const int mb  = (warp >> 3) * 64;   // batch offset  (2 groups x 64)
    const int r   = lane >> 2;          // 0..7 (mma groupID)
    const int c   = lane & 3;           // 0..3 (mma threadID-in-group)

    const int m0 = blockIdx.x * BM;
    const int n0 = blockIdx.y * BN;
    const int z  = blockIdx.z;
    const size_t kbase = (size_t)z * KSLICE;
    const int i0 = z * (KSLICE / D_SZ);

    // per-thread W2 staging coords (128 rows x 8 float4-segs = 1024 segs, 2 each)
    const int srow0 = (tid * 2)     >> 3;
    const int skv0  = ((tid * 2)     & 7) * 4;
    const int srow1 = (tid * 2 + 1) >> 3;
    const int skv1  = ((tid * 2 + 1) & 7) * 4;
    const uint32_t sB = smem_u32(Bsm);

    float acc[8][4];                    // [batch-subtile][frag]
#pragma unroll
    for (int nb = 0; nb < 8; ++nb)
#pragma unroll
        for (int q = 0; q < 4; ++q) acc[nb][q] = 0.f;

    // ht register cache, per j-block: htv[nb][2ks+h] = ht[mb+nb*8+r][j0+ks*8+c+4h]
    float htv[8][8];

    // ---- prologue: issue pairs 0 and 1 (chunks 0..3; jc=0, i_loc=chunk) ----
#pragma unroll
    for (int pp = 0; pp < 2; ++pp) {
#pragma unroll
        for (int s = 0; s < 2; ++s) {
            int pc = pp * 2 + s;
            size_t gcol = kbase + (size_t)pc * D_SZ;
            uint32_t dbase = sB + (uint32_t)(pc * B_WORDS) * 4;
            cp_async16(dbase + (uint32_t)(srow0 * LDT + skv0) * 4,
                       W2 + (size_t)(n0 + srow0) * K_WIDE + gcol + skv0);
            cp_async16(dbase + (uint32_t)(srow1 * LDT + skv1) * 4,
                       W2 + (size_t)(n0 + srow1) * K_WIDE + gcol + skv1);
        }
        cp_commit();                                // one group per PAIR
    }

    int buf0 = 0;   // first buffer of current pair:  (2t) % 6
    int pbf0 = 4;   // first buffer of prefetch pair: (2t+4) % 6

#pragma unroll 1
    for (int t = 0; t < NPAIR; ++t) {
        const int ch = 2 * t;
        cp_wait1();          // pair t's group complete (pair t+1 may pend)
        __syncthreads();     // W2 visible; all warps done with iter t-1

        // ---- stage hs i-group (every 4 pairs) / ht j-block (every 64) ----
        if ((ch & 7) == 0) {
            const int jc = ch >> 7;
            const int ib = (ch >> 3) & 15;
            if ((ch & 127) == 0) {
#pragma unroll
                for (int s = 0; s < 2; ++s) {
                    int seg = tid * 2 + s;
                    int row = seg >> 3;
                    int kv  = (seg & 7) * 4;
                    float4 v = *(const float4*)(ht + (size_t)(m0 + row) * D_SZ + jc * BKC + kv);
                    *(float4*)&Hts[row * LDT + kv] = v;
                }
            }
            {
                // Hss[m][ii] layout: thread -> (m, ii-pair); gmem float2 is
                // contiguous (ii fastest in hs row) and 8B-aligned (even ii)
                int m  = tid >> 2;
                int pr = (tid & 3) * 2;
                float2 hv = *(const float2*)(hs + (size_t)(m0 + m) * D_SZ + i0 + ib * IPG + pr);
                hv.x *= HS_COMP;   // cancels expected tf32-truncation bias
                hv.y *= HS_COMP;   // of both mma operands in each product
                Hss[m * HSS_LD + pr]     = hv.x;
                Hss[m * HSS_LD + pr + 1] = hv.y;
            }
            __syncthreads();
            if ((ch & 127) == 0) {
#pragma unroll
                for (int nb = 0; nb < 8; ++nb)
#pragma unroll
                    for (int q = 0; q < 8; ++q) {
                        int col = (q >> 1) * 8 + c + 4 * (q & 1);
                        htv[nb][q] = Hts[(mb + nb * 8 + r) * LDT + col];
                    }
            }
        }

        // ---- compute BOTH chunks of pair t (same htv; different hs, W2) ----
        const int iibase = ch & 7;          // even; pair is (iibase, iibase+1)
#pragma unroll
        for (int sub = 0; sub < 2; ++sub) {
            const float* Wb = Bsm + (buf0 + sub) * B_WORDS;
            float hsx[8];
#pragma unroll
            for (int nb = 0; nb < 8; ++nb)
                hsx[nb] = Hss[(mb + nb * 8 + r) * HSS_LD + iibase + sub];

#pragma unroll
            for (int ks = 0; ks < 4; ++ks) {
                float a[4];   // W2 fragment: rows wn2+r/+8, k-cols ks*8+c/+4
                a[0] = Wb[(wn2 + r    ) * LDT + ks * 8 + c];
                a[1] = Wb[(wn2 + r + 8) * LDT + ks * 8 + c];
                a[2] = Wb[(wn2 + r    ) * LDT + ks * 8 + c + 4];
                a[3] = Wb[(wn2 + r + 8) * LDT + ks * 8 + c + 4];
#pragma unroll
                for (int nb = 0; nb < 8; ++nb) {
                    float b0 = hsx[nb] * htv[nb][2 * ks];      // k = c
                    float b1 = hsx[nb] * htv[nb][2 * ks + 1];  // k = c+4
                    mma_tf32(acc[nb], a, b0, b1);
                }
            }
        }

        // ---- issue pair t+2 into (pbf0, pbf0+1) (safe: see header) ----
#pragma unroll
        for (int sub = 0; sub < 2; ++sub) {
            int cn = ch + 4 + sub;
            if (cn < NCH) {
                int jcn   = cn >> 7;
                int ilocn = ((cn >> 3) & 15) * IPG + (cn & 7);
                size_t gcol = kbase + (size_t)ilocn * D_SZ + jcn * BKC;
                uint32_t dbase = sB + (uint32_t)((pbf0 + sub) * B_WORDS) * 4;
                cp_async16(dbase + (uint32_t)(srow0 * LDT + skv0) * 4,
                           W2 + (size_t)(n0 + srow0) * K_WIDE + gcol + skv0);
                cp_async16(dbase + (uint32_t)(srow1 * LDT + skv1) * 4,
                           W2 + (size_t)(n0 + srow1) * K_WIDE + gcol + skv1);
            }
        }
        cp_commit();   // exactly one group per iteration (possibly empty)

        buf0 += 2; if (buf0 >= NBUF) buf0 -= NBUF;
        pbf0 += 2; if (pbf0 >= NBUF) pbf0 -= NBUF;
    }

    // ---- epilogue (transposed D): mma m-dim = output col, n-dim = batch row ----
    // d0=(r,2c) d1=(r,2c+1) d2=(r+8,2c) d3=(r+8,2c+1) in (W2row, batch) coords
#pragma unroll
    for (int nb = 0; nb < 8; ++nb) {
        int brow = m0 + mb + nb * 8 + 2 * c;            // batch row (d0/d2)
        int col  = N_OUT + n0 + wn2 + r;                // output column (d0/d1)
        atomicAdd(&out[(size_t)brow       * OUT_STR + col    ], acc[nb][0]);
        atomicAdd(&out[(size_t)(brow + 1) * OUT_STR + col    ], acc[nb][1]);
        atomicAdd(&out[(size_t)brow       * OUT_STR + col + 8], acc[nb][2]);
        atomicAdd(&out[(size_t)(brow + 1) * OUT_STR + col + 8], acc[nb][3]);
    }
}

// ---------------------------------------------------------------------------
extern "C" void kernel_launch(void* const* d_in, const int* in_sizes, int n_in,
                              void* d_out, int out_size)
{
    const float* hs  = (const float*)d_in[0];
    const float* ht  = (const float*)d_in[1];
    const float* WL  = (const float*)d_in[2];
    const float* bL  = (const float*)d_in[3];
    const float* W2  = (const float*)d_in[4];
    const float* bL2 = (const float*)d_in[5];
    float* out = (float*)d_out;

    // deep path + bias init of wide region (same-stream ordering -> graph edge)
    deep_kernel<<<dim3(BATCH / DBM, N_OUT / DBN), 256>>>(hs, ht, WL, bL, bL2, out);

    // dynamic smem (~134 KB); attribute set is not an allocation
    cudaFuncSetAttribute(wide_kernel, cudaFuncAttributeMaxDynamicSharedMemorySize, SMEM_BYTES);

    // wide path: M fastest -> 8 co-scheduled M-CTAs share W2 slices in L2
    wide_kernel<<<dim3(BATCH / BM, N_OUT / BN, KSPLIT), NTH, SMEM_BYTES>>>(hs, ht, W2, out);
}

// round 12
// speedup vs baseline: 1.0881x; 1.0881x over previous
#include <cuda_runtime.h>
#include <cstdint>

// ---------------------------------------------------------------------------
// Problem constants
// ---------------------------------------------------------------------------
#define BATCH   1024
#define D_SZ    384
#define K_WIDE  (D_SZ * D_SZ)      // 147456
#define N_OUT   (2 * D_SZ)         // 768
#define OUT_STR (4 * D_SZ)         // 1536

// ---------------------------------------------------------------------------
// Wide-path GEMM config: M=1024 N=768 K=147456, A = hs x ht generated on-fly
// R12: two resident CTAs per SM (BN 128->64, 256 threads, 78KB smem each).
// All single-CTA stall-decorrelation attempts failed (R6/R7/R9/R10); two
// independent CTAs with different tiles phase-shift their stage/drain
// windows so the tensor pipe stays fed.
// ---------------------------------------------------------------------------
#define BM      128
#define BN      64
#define BKC     32                  // k-floats per chunk
#define KSPLIT  3
#define KSLICE  (K_WIDE / KSPLIT)   // 49152 = 128 i-values
#define IPG     8                   // i-values per hs staging group
#define NCH     (KSLICE / BKC)      // 1536 chunks per CTA
#define NPAIR   (NCH / 2)           // 768 pipeline iterations (2 chunks each)
#define LDT     36                  // row stride words: 32 + 4 pad (conflict-free)
#define NTH     256                 // 8 warps = 4(m) x 2(n), warp tile 32x32
#define NBUF    6                   // 3-deep ring of chunk PAIRS

// Truncation-bias compensation (R8, kept): both mma operands HW-truncate
// fp32->tf32; pre-scaling hs by (1 + 2^-10 * ln2) cancels the expected
// relative bias of BOTH operands in each product. rel_err ~3.4e-4 measured.
#define HS_COMP 1.000677f

#define B_WORDS   (BN * LDT)            // per B chunk buffer (2304 words)
#define HTS_WORDS (BM * LDT)
#define HSS_WORDS (IPG * BM)
#define SMEM_WORDS (NBUF * B_WORDS + HTS_WORDS + HSS_WORDS)
#define SMEM_BYTES (SMEM_WORDS * 4)     // ~78 KB -> 2 CTAs/SM (156 <= 228 KB)

__device__ __forceinline__ void cp_async16(uint32_t dst, const void* src) {
    asm volatile("cp.async.cg.shared.global [%0], [%1], 16;" :: "r"(dst), "l"(src) : "memory");
}
__device__ __forceinline__ void cp_commit() {
    asm volatile("cp.async.commit_group;" ::: "memory");
}
__device__ __forceinline__ void cp_wait1() {
    asm volatile("cp.async.wait_group 1;" ::: "memory");
}
__device__ __forceinline__ uint32_t smem_u32(const void* p) {
    uint32_t a;
    asm("{ .reg .u64 t; cvta.to.shared.u64 t, %1; cvt.u32.u64 %0, t; }" : "=r"(a) : "l"(p));
    return a;
}

// m16n8k8 tf32 mma; BOTH operands HW-truncated from fp32 bits
__device__ __forceinline__ void mma_tf32(float c[4], const float a[4], float b0, float b1) {
    asm volatile(
        "mma.sync.aligned.m16n8k8.row.col.f32.tf32.tf32.f32 "
        "{%0,%1,%2,%3}, {%4,%5,%6,%7}, {%8,%9}, {%0,%1,%2,%3};\n"
        : "+f"(c[0]), "+f"(c[1]), "+f"(c[2]), "+f"(c[3])
        : "r"(__float_as_uint(a[0])), "r"(__float_as_uint(a[1])),
          "r"(__float_as_uint(a[2])), "r"(__float_as_uint(a[3])),
          "r"(__float_as_uint(b0)), "r"(__float_as_uint(b1)));
}

// ---------------------------------------------------------------------------
// Deep path (passed R1, unchanged):  g = [hs|ht] @ W_L^T + b_L -> out[:,0:768]
// Also initializes out[:,768:1536] = b_L2 for the wide kernel's atomics.
// ---------------------------------------------------------------------------
#define DBM 64
#define DBN 64
#define DBK 16

__global__ __launch_bounds__(256)
void deep_kernel(const float* __restrict__ hs, const float* __restrict__ ht,
                 const float* __restrict__ WL, const float* __restrict__ bL,
                 const float* __restrict__ bL2, float* __restrict__ out)
{
    __shared__ float Xs[DBK][DBM + 8];
    __shared__ float Ws[DBK][DBN + 8];

    const int tid = threadIdx.x;
    const int tx  = tid & 15;
    const int ty  = tid >> 4;
    const int m0  = blockIdx.x * DBM;
    const int n0  = blockIdx.y * DBN;

    float acc[4][4];
#pragma unroll
    for (int i = 0; i < 4; ++i)
#pragma unroll
        for (int j = 0; j < 4; ++j) acc[i][j] = 0.f;

    for (int k0 = 0; k0 < 2 * D_SZ; k0 += DBK) {
        __syncthreads();
#pragma unroll
        for (int q = 0; q < 4; ++q) {
            int e  = tid + 256 * q;
            int kk = e & 15;
            int mm = e >> 4;
            int gk = k0 + kk;
            float xv = (gk < D_SZ) ? hs[(m0 + mm) * D_SZ + gk]
                                   : ht[(m0 + mm) * D_SZ + (gk - D_SZ)];
            Xs[kk][mm] = xv;
            Ws[kk][mm] = WL[(size_t)(n0 + mm) * (2 * D_SZ) + gk];
        }
        __syncthreads();
#pragma unroll
        for (int kk = 0; kk < DBK; ++kk) {
            float4 av = *(const float4*)&Xs[kk][ty * 4];
            float4 bv = *(const float4*)&Ws[kk][tx * 4];
            float a[4] = {av.x, av.y, av.z, av.w};
            float b[4] = {bv.x, bv.y, bv.z, bv.w};
#pragma unroll
            for (int i = 0; i < 4; ++i)
#pragma unroll
                for (int j = 0; j < 4; ++j) acc[i][j] += a[i] * b[j];
        }
    }

#pragma unroll
    for (int i = 0; i < 4; ++i) {
        int row = m0 + ty * 4 + i;
#pragma unroll
        for (int j = 0; j < 4; ++j) {
            int col = n0 + tx * 4 + j;
            out[(size_t)row * OUT_STR + col]         = acc[i][j] + bL[col];
            out[(size_t)row * OUT_STR + N_OUT + col] = bL2[col];
        }
    }
}

// ---------------------------------------------------------------------------
// Wide kernel: 256 threads = 8 warps (4m x 2n), warp tile 32x32 (the proven
// R9 shape), BN=64, 2 CTAs resident per SM.
// A fragments: ht frags (per 64-pair j-block, registers) x hs scalars
// (per 4-pair i-group, SMEM, pre-scaled by HS_COMP).
// B: cp.async ring, two chunks per pipeline iteration (one group/wait/barrier
// per pair; pairs share a j-block so htr is reused).
// Ring: NBUF=6 chunk buffers = 3 pairs. Iter t computes bufs (2t)%6,(2t+1)%6,
// then issues pair t+2 into (2t+4)%6,(2t+5)%6 — last read at iter t-1; the
// barrier at top of iter t bounds warp drift.
// ---------------------------------------------------------------------------
__global__ __launch_bounds__(NTH, 2)
void wide_kernel(const float* __restrict__ hs, const float* __restrict__ ht,
                 const float* __restrict__ W2, float* __restrict__ out)
{
    extern __shared__ __align__(16) float smem[];
    float* Bsm = smem;                          // NBUF * BN * LDT
    float* Hts = smem + NBUF * B_WORDS;         // BM * LDT
    float* Hss = Hts + HTS_WORDS;               // IPG * BM

    const int tid  = threadIdx.x;
    const int lane = tid & 31;
    const int warp = tid >> 5;
    const int wm = (warp & 3) * 32;     // warp m offset (4 m-warps)
    const int wn = (warp >> 2) * 32;    // warp n offset (2 n-warps)
    const int r  = lane >> 2;           // 0..7
    const int c  = lane & 3;            // 0..3

    const int m0 = blockIdx.x * BM;
    const int n0 = blockIdx.y * BN;
    const int z  = blockIdx.z;
    const size_t kbase = (size_t)z * KSLICE;
    const int i0 = z * (KSLICE / D_SZ);

    // per-thread B staging coords (64 rows x 8 float4-segs = 512 segs, 2 each)
    const int srow0 = (tid * 2)     >> 3;
    const int skv0  = ((tid * 2)     & 7) * 4;
    const int srow1 = (tid * 2 + 1) >> 3;
    const int skv1  = ((tid * 2 + 1) & 7) * 4;
    const uint32_t sB = smem_u32(Bsm);

    float acc[2][4][4];
#pragma unroll
    for (int mi = 0; mi < 2; ++mi)
#pragma unroll
        for (int ni = 0; ni < 4; ++ni)
#pragma unroll
            for (int q = 0; q < 4; ++q) acc[mi][ni][q] = 0.f;

    float htr[4][2][4];   // ht fragments [kstep][mi][frag], per j-block

    // ---- prologue: issue pairs 0 and 1 (chunks 0..3; jc=0, i_loc=chunk) ----
#pragma unroll
    for (int pp = 0; pp < 2; ++pp) {
#pragma unroll
        for (int s = 0; s < 2; ++s) {
            int pc = pp * 2 + s;
            size_t gcol = kbase + (size_t)pc * D_SZ;
            uint32_t dbase = sB + (uint32_t)(pc * B_WORDS) * 4;
            cp_async16(dbase + (uint32_t)(srow0 * LDT + skv0) * 4,
                       W2 + (size_t)(n0 + srow0) * K_WIDE + gcol + skv0);
            cp_async16(dbase + (uint32_t)(srow1 * LDT + skv1) * 4,
                       W2 + (size_t)(n0 + srow1) * K_WIDE + gcol + skv1);
        }
        cp_commit();                                // one group per PAIR
    }

    int buf0 = 0;   // first buffer of current pair:  (2t) % 6
    int pbf0 = 4;   // first buffer of prefetch pair: (2t+4) % 6

#pragma unroll 1
    for (int t = 0; t < NPAIR; ++t) {
        const int ch = 2 * t;
        cp_wait1();          // pair t's group complete (pair t+1 may pend)
        __syncthreads();     // B visible; all warps done with iter t-1

        // ---- stage hs i-group (every 4 pairs) / ht j-block (every 64) ----
        if ((ch & 7) == 0) {
            const int jc = ch >> 7;
            const int ib = (ch >> 3) & 15;
            if ((ch & 127) == 0) {
                // 128 rows x 8 segs = 1024 segs / 256 threads = 4 each
#pragma unroll
                for (int s = 0; s < 4; ++s) {
                    int seg = tid * 4 + s;
                    int row = seg >> 3;
                    int kv  = (seg & 7) * 4;
                    float4 v = *(const float4*)(ht + (size_t)(m0 + row) * D_SZ + jc * BKC + kv);
                    *(float4*)&Hts[row * LDT + kv] = v;
                }
            }
            // 8 ii x 128 m = 1024 / 256 threads = 4 each
#pragma unroll
            for (int s = 0; s < 4; ++s) {
                int e  = tid + NTH * s;
                int ii = e >> 7;
                int m  = e & 127;
                // HS_COMP cancels expected tf32-truncation bias of both operands
                Hss[ii * BM + m] = __ldg(hs + (size_t)(m0 + m) * D_SZ + i0 + ib * IPG + ii) * HS_COMP;
            }
            __syncthreads();
            if ((ch & 127) == 0) {
#pragma unroll
                for (int ks = 0; ks < 4; ++ks)
#pragma unroll
                    for (int mi = 0; mi < 2; ++mi) {
                        int mrow = wm + mi * 16;
                        htr[ks][mi][0] = Hts[(mrow + r)     * LDT + ks * 8 + c];
                        htr[ks][mi][1] = Hts[(mrow + r + 8) * LDT + ks * 8 + c];
                        htr[ks][mi][2] = Hts[(mrow + r)     * LDT + ks * 8 + c + 4];
                        htr[ks][mi][3] = Hts[(mrow + r + 8) * LDT + ks * 8 + c + 4];
                    }
            }
        }

        // ---- compute BOTH chunks of pair t (same htr; different hs, B) ----
        const int iibase = ch & 7;          // even; pair is (iibase, iibase+1)
#pragma unroll
        for (int sub = 0; sub < 2; ++sub) {
            const float* Bb = Bsm + (buf0 + sub) * B_WORDS;
            const int ii = iibase + sub;
            float hsv[2][2];
            hsv[0][0] = Hss[ii * BM + wm + r];
            hsv[0][1] = Hss[ii * BM + wm + r + 8];
            hsv[1][0] = Hss[ii * BM + wm + 16 + r];
            hsv[1][1] = Hss[ii * BM + wm + 16 + r + 8];

#pragma unroll
            for (int ks = 0; ks < 4; ++ks) {
                float a[2][4];
#pragma unroll
                for (int mi = 0; mi < 2; ++mi) {
                    a[mi][0] = hsv[mi][0] * htr[ks][mi][0];
                    a[mi][1] = hsv[mi][1] * htr[ks][mi][1];
                    a[mi][2] = hsv[mi][0] * htr[ks][mi][2];
                    a[mi][3] = hsv[mi][1] * htr[ks][mi][3];
                }
#pragma unroll
                for (int ni = 0; ni < 4; ++ni) {
                    int nrow = wn + ni * 8 + r;
                    float b0 = Bb[nrow * LDT + ks * 8 + c];
                    float b1 = Bb[nrow * LDT + ks * 8 + c + 4];
                    mma_tf32(acc[0][ni], a[0], b0, b1);
                    mma_tf32(acc[1][ni], a[1], b0, b1);
                }
            }
        }

        // ---- issue pair t+2 into (pbf0, pbf0+1) (safe: see header) ----
#pragma unroll
        for (int sub = 0; sub < 2; ++sub) {
            int cn = ch + 4 + sub;
            if (cn < NCH) {
                int jcn   = cn >> 7;
                int ilocn = ((cn >> 3) & 15) * IPG + (cn & 7);
                size_t gcol = kbase + (size_t)ilocn * D_SZ + jcn * BKC;
                uint32_t dbase = sB + (uint32_t)((pbf0 + sub) * B_WORDS) * 4;
                cp_async16(dbase + (uint32_t)(srow0 * LDT + skv0) * 4,
                           W2 + (size_t)(n0 + srow0) * K_WIDE + gcol + skv0);
                cp_async16(dbase + (uint32_t)(srow1 * LDT + skv1) * 4,
                           W2 + (size_t)(n0 + srow1) * K_WIDE + gcol + skv1);
            }
        }
        cp_commit();   // exactly one group per iteration (possibly empty)

        buf0 += 2; if (buf0 >= NBUF) buf0 -= NBUF;
        pbf0 += 2; if (pbf0 >= NBUF) pbf0 -= NBUF;
    }

    // ---- epilogue: atomic accumulate onto bias-initialized out[:,768:1536] ----
#pragma unroll
    for (int mi = 0; mi < 2; ++mi) {
#pragma unroll
        for (int ni = 0; ni < 4; ++ni) {
            int row = m0 + wm + mi * 16 + r;
            int col = N_OUT + n0 + wn + ni * 8 + 2 * c;
            float* p0 = &out[(size_t)row * OUT_STR + col];
            atomicAdd(p0,     acc[mi][ni][0]);
            atomicAdd(p0 + 1, acc[mi][ni][1]);
            float* p1 = &out[(size_t)(row + 8) * OUT_STR + col];
            atomicAdd(p1,     acc[mi][ni][2]);
            atomicAdd(p1 + 1, acc[mi][ni][3]);
        }
    }
}

// ---------------------------------------------------------------------------
extern "C" void kernel_launch(void* const* d_in, const int* in_sizes, int n_in,
                              void* d_out, int out_size)
{
    const float* hs  = (const float*)d_in[0];
    const float* ht  = (const float*)d_in[1];
    const float* WL  = (const float*)d_in[2];
    const float* bL  = (const float*)d_in[3];
    const float* W2  = (const float*)d_in[4];
    const float* bL2 = (const float*)d_in[5];
    float* out = (float*)d_out;

    // deep path + bias init of wide region (same-stream ordering -> graph edge)
    deep_kernel<<<dim3(BATCH / DBM, N_OUT / DBN), 256>>>(hs, ht, WL, bL, bL2, out);

    // dynamic smem ~78 KB/CTA -> 2 CTAs resident; attribute set is not an alloc
    cudaFuncSetAttribute(wide_kernel, cudaFuncAttributeMaxDynamicSharedMemorySize, SMEM_BYTES);

    // grid (8 M, 12 N, 3 K) = 288 CTAs ~= 2 per SM, one wave
    wide_kernel<<<dim3(BATCH / BM, N_OUT / BN, KSPLIT), NTH, SMEM_BYTES>>>(hs, ht, W2, out);
}